// round 11
// baseline (speedup 1.0000x reference)
#include <cuda_runtime.h>
#include <cuda_bf16.h>

#define BB   2
#define CC   128
#define HCH  64
#define TT   5
#define TC   4
#define HH   48
#define WIW  48
#define HW   2304
#define NKEY 196

// Scratch (device globals; no allocations allowed)
__device__ float theta_s[BB * HW * HCH];                          // [b][p][h] fp32, pre-scaled by 8
__device__ __align__(16) __nv_bfloat16 phi_b[BB * TC * HW * HCH]; // [pix][h] bf16
__device__ __align__(16) __nv_bfloat16 g_b[BB * TC * HW * HCH];   // [pix][slot] bf16, slot(h)=4*(h&15)+(h>>4)
__device__ float y_s[BB * HW * HCH];                              // [b][p][hc]

// packed f32x2 helpers (sm_103a)
#define FMA_F32X2(d, a, b) \
  asm("fma.rn.f32x2 %0, %1, %2, %0;" : "+l"(d) : "l"(a), "l"(b))
#define PACK_F32X2(out, lo, hi) \
  asm("mov.b64 %0, {%1, %2};" : "=l"(out) : "r"(__float_as_uint(lo)), "r"(__float_as_uint(hi)))
#define UNPACK_F32X2(lo, hi, in) \
  do { unsigned _l, _h; asm("mov.b64 {%0, %1}, %2;" : "=r"(_l), "=r"(_h) : "l"(in)); \
       lo = __uint_as_float(_l); hi = __uint_as_float(_h); } while (0)

__device__ __forceinline__ unsigned pack_bf2(float a, float b) {
  __nv_bfloat162 h = __floats2bfloat162_rn(a, b);
  return *(unsigned*)&h;
}

// ---------------------------------------------------------------------------
// Kernel 1: projections. Tile 64px x {64|128}n, 256 threads, grid (36,B,5).
// NO x smem tile: 8 warps/CTA read the same 16 x-lines per c -> L1 broadcast.
// dyn smem = wsm[128c][132n] fp32 = 67.5KB -> 3 CTA/SM -> single wave.
// ---------------------------------------------------------------------------
__global__ __launch_bounds__(256, 3) void proj_kernel(
    const float* __restrict__ x,
    const float* __restrict__ w_theta,
    const float* __restrict__ w_phi,
    const float* __restrict__ w_g) {
  extern __shared__ float wsm[];   // [c][n] 128 x 132 (padded)

  const int tile = blockIdx.x, b = blockIdx.y, t = blockIdx.z;
  const int tid = threadIdx.x;
  const int p0 = tile * 64;

  if (t == 0) {
    for (int i = tid; i < 64 * 128; i += 256) {
      int n = i >> 7, c = i & 127;
      wsm[c * 132 + n] = w_theta[i];
    }
  } else {
    for (int i = tid; i < 128 * 128; i += 256) {
      int n = i >> 7, c = i & 127;
      wsm[c * 132 + n] = (n < 64) ? w_phi[n * 128 + c] : w_g[(n - 64) * 128 + c];
    }
  }
  __syncthreads();

  const int px4 = (tid & 15) * 4;
  const float* xg = x + ((size_t)(b * CC) * TT + t) * HW + p0 + px4;
  const size_t cstr = (size_t)TT * HW;   // per-channel stride in elements

  if (t == 0) {
    const int n0 = (tid >> 4) * 4;
    unsigned long long acc[4][2];
#pragma unroll
    for (int i = 0; i < 4; i++) { acc[i][0] = 0ull; acc[i][1] = 0ull; }

#pragma unroll 4
    for (int c = 0; c < 128; c++) {
      float4 xv = *(const float4*)(xg + c * cstr);
      ulonglong2 wp = *(const ulonglong2*)(wsm + c * 132 + n0);
      float xa[4] = {xv.x, xv.y, xv.z, xv.w};
      unsigned long long xd[4];
#pragma unroll
      for (int i = 0; i < 4; i++) PACK_F32X2(xd[i], xa[i], xa[i]);
#pragma unroll
      for (int i = 0; i < 4; i++) {
        FMA_F32X2(acc[i][0], xd[i], wp.x);
        FMA_F32X2(acc[i][1], xd[i], wp.y);
      }
    }
#pragma unroll
    for (int i = 0; i < 4; i++) {
      float f0, f1, f2, f3;
      UNPACK_F32X2(f0, f1, acc[i][0]);
      UNPACK_F32X2(f2, f3, acc[i][1]);
      int pix = p0 + px4 + i;
      *(float4*)(theta_s + (size_t)(b * HW + pix) * 64 + n0) =
          make_float4(8.f * f0, 8.f * f1, 8.f * f2, 8.f * f3);
    }
  } else {
    const int n0 = (tid >> 4) * 8;
    unsigned long long acc[4][4];
#pragma unroll
    for (int i = 0; i < 4; i++)
#pragma unroll
      for (int j = 0; j < 4; j++) acc[i][j] = 0ull;

#pragma unroll 4
    for (int c = 0; c < 128; c++) {
      float4 xv = *(const float4*)(xg + c * cstr);
      ulonglong2 wa = *(const ulonglong2*)(wsm + c * 132 + n0);
      ulonglong2 wb = *(const ulonglong2*)(wsm + c * 132 + n0 + 4);
      unsigned long long wp[4] = {wa.x, wa.y, wb.x, wb.y};
      float xa[4] = {xv.x, xv.y, xv.z, xv.w};
      unsigned long long xd[4];
#pragma unroll
      for (int i = 0; i < 4; i++) PACK_F32X2(xd[i], xa[i], xa[i]);
#pragma unroll
      for (int i = 0; i < 4; i++)
#pragma unroll
        for (int j = 0; j < 4; j++) FMA_F32X2(acc[i][j], xd[i], wp[j]);
    }

    const int nn = n0 & 63;
    const size_t rowb = (size_t)((b * TC + (t - 1)) * HW);
#pragma unroll
    for (int i = 0; i < 4; i++) {
      float f[8];
#pragma unroll
      for (int j = 0; j < 4; j++) UNPACK_F32X2(f[2 * j], f[2 * j + 1], acc[i][j]);
      int pix = p0 + px4 + i;
      if (n0 < 64) {
        // phi: channel-contiguous
        uint4 s;
        s.x = pack_bf2(f[0], f[1]); s.y = pack_bf2(f[2], f[3]);
        s.z = pack_bf2(f[4], f[5]); s.w = pack_bf2(f[6], f[7]);
        *(uint4*)(phi_b + (rowb + pix) * 64 + nn) = s;
      } else {
        // g: permuted  slot(h) = 4*(h&15) + (h>>4)
        __nv_bfloat16* gd = g_b + (rowb + pix) * 64;
#pragma unroll
        for (int j = 0; j < 8; j++) {
          int hch = nn + j;
          int slot = ((hch & 15) << 2) | (hch >> 4);
          gd[slot] = __float2bfloat16(f[j]);
        }
      }
    }
  }
}

// ---------------------------------------------------------------------------
// Kernel 2: attention, 2 pixels per warp (16 lanes each), 16 px/block, grid 288.
// Lane l (0..15) of a half-warp handles channels h = l, l+16, l+32, l+48
// (shared rotation class 4l mod 64). g_b is slot-permuted so those 4 channels
// are one aligned 8B load.
// ---------------------------------------------------------------------------
__global__ __launch_bounds__(256, 2) void attn_kernel() {
  __shared__ float logits[16][200];
  __shared__ int   ofs[16][196];
  __shared__ float ysm[16][64];
  const int wid = threadIdx.x >> 5, lane = threadIdx.x & 31;
  const int half = lane >> 4, l = lane & 15;
  const int slot = wid * 2 + half;
  const int pid = blockIdx.x * 16 + slot;
  const int b = pid / HW, p = pid % HW;
  const int py = p / WIW, px = p % WIW;
  const int cp = l & 3, kg = l >> 2;

  // per-key pixel offsets (element offset of channel 0)
#pragma unroll
  for (int j = 0; j < 13; j++) {
    int rem = l + j * 16;
    if (rem < NKEY) {
      int t = rem / 49, r = rem % 49;
      int dy = r / 7, dx = r % 7;
      int yy = min(max(py + dy - 3, 0), HH - 1);
      int xx = min(max(px + dx - 3, 0), WIW - 1);
      ofs[slot][rem] = ((b * TC + t) * HW + yy * WIW + xx) * 64;
    }
  }
  __syncwarp();

  // ---- Pass 1: logits (4 keys x 4 channel-quarters per half-warp) ----
  const float* qp = theta_s + (size_t)(b * HW + p) * 64 + cp * 16;
  float q[16];
#pragma unroll
  for (int j = 0; j < 4; j++) {
    float4 qv = *(const float4*)(qp + j * 4);
    q[j*4+0] = qv.x; q[j*4+1] = qv.y; q[j*4+2] = qv.z; q[j*4+3] = qv.w;
  }

#pragma unroll 7
  for (int it = 0; it < 49; it++) {
    int k = it * 4 + kg;
    const uint4* ph = (const uint4*)(phi_b + ofs[slot][k]) + cp * 2;
    uint4 A = ph[0], B2 = ph[1];
    unsigned r[8] = {A.x, A.y, A.z, A.w, B2.x, B2.y, B2.z, B2.w};
    float s = 0.f;
#pragma unroll
    for (int w = 0; w < 8; w++) {
      float lo = __uint_as_float(r[w] << 16);
      float hi = __uint_as_float(r[w] & 0xffff0000u);
      s = fmaf(q[2*w], lo, fmaf(q[2*w+1], hi, s));
    }
    s += __shfl_xor_sync(0xffffffffu, s, 1);
    s += __shfl_xor_sync(0xffffffffu, s, 2);
    if (cp == 0) logits[slot][k] = s;
  }
  __syncwarp();

  // ---- Softmax over 196 within half-warp ----
  float lv[13], m = -1e30f;
#pragma unroll
  for (int j = 0; j < 13; j++) {
    int idx = l + j * 16;
    lv[j] = (idx < NKEY) ? logits[slot][idx] : -1e30f;
    m = fmaxf(m, lv[j]);
  }
#pragma unroll
  for (int off = 8; off >= 1; off >>= 1)
    m = fmaxf(m, __shfl_xor_sync(0xffffffffu, m, off));
  float ssum = 0.f;
#pragma unroll
  for (int j = 0; j < 13; j++) {
    int idx = l + j * 16;
    if (idx < NKEY) {
      float e = __expf(lv[j] - m);
      logits[slot][idx] = e;
      ssum += e;
    }
  }
#pragma unroll
  for (int off = 8; off >= 1; off >>= 1)
    ssum += __shfl_xor_sync(0xffffffffu, ssum, off);
  const float rinv = 1.f / ssum;
  __syncwarp();

  // ---- Pass 2: scrambled AV. h=l+16m -> weight logits[3l + 49m + ((4l+rem)>>6)],
  //      g slots 4l..4l+3, bucket (rem)&63 with rotation 4l applied at scatter.
  float acc[64];
#pragma unroll
  for (int s = 0; s < 64; s++) acc[s] = 0.f;

  const int wl = 3 * l, fl = 4 * l;
#pragma unroll 1
  for (int seg = 0; seg < 3; seg++) {
    const int rb = seg * 64;
#pragma unroll
    for (int s = 0; s < 64; s++) {
      int rem = rb + s;
      int o = ofs[slot][rem];
      uint2 v = *(const uint2*)(g_b + o + fl);
      int wb = wl + seg + ((fl + s) >> 6);
      float w0 = logits[slot][wb];
      float w1 = logits[slot][wb + 49];
      float w2 = logits[slot][wb + 98];
      float w3 = logits[slot][wb + 147];
      float g0 = __uint_as_float(v.x << 16);
      float g1 = __uint_as_float(v.x & 0xffff0000u);
      float g2 = __uint_as_float(v.y << 16);
      float g3 = __uint_as_float(v.y & 0xffff0000u);
      acc[s] = fmaf(w0, g0, fmaf(w1, g1, fmaf(w2, g2, fmaf(w3, g3, acc[s]))));
    }
  }
  // tail rem = 192..195  (seg=3)
#pragma unroll
  for (int s = 0; s < 4; s++) {
    int rem = 192 + s;
    int o = ofs[slot][rem];
    uint2 v = *(const uint2*)(g_b + o + fl);
    int wb = wl + 3 + ((fl + s) >> 6);
    float w0 = logits[slot][wb];
    float w1 = logits[slot][wb + 49];
    float w2 = logits[slot][wb + 98];
    float w3 = logits[slot][wb + 147];
    float g0 = __uint_as_float(v.x << 16);
    float g1 = __uint_as_float(v.x & 0xffff0000u);
    float g2 = __uint_as_float(v.y << 16);
    float g3 = __uint_as_float(v.y & 0xffff0000u);
    acc[s] = fmaf(w0, g0, fmaf(w1, g1, fmaf(w2, g2, fmaf(w3, g3, acc[s]))));
  }

  // ---- scatter rotated accs into ysm (16 lanes per px, distinct buckets) ----
#pragma unroll
  for (int j = 0; j < 4; j++) ysm[slot][l + 16 * j] = 0.f;
  __syncwarp();
#pragma unroll
  for (int s = 0; s < 64; s++)
    ysm[slot][(fl + s) & 63] += acc[s];
  __syncwarp();

  float4 yo;
  yo.x = ysm[slot][fl + 0] * rinv;
  yo.y = ysm[slot][fl + 1] * rinv;
  yo.z = ysm[slot][fl + 2] * rinv;
  yo.w = ysm[slot][fl + 3] * rinv;
  *(float4*)(y_s + (size_t)(b * HW + p) * 64 + fl) = yo;
}

// ---------------------------------------------------------------------------
// Kernel 3 (raw-reshape of Y[B,HW,64] to [B,64,1,48,48]):
// with pix = u*64+v:  out[b][c][pix] = x[b][c][0][pix]
//                     + sum_h w_out[c][h] * Y[b][h*36 + u][v]
// ---------------------------------------------------------------------------
__global__ __launch_bounds__(256) void outproj_kernel(
    const float* __restrict__ x,
    const float* __restrict__ w_out,
    float* __restrict__ out) {
  extern __shared__ float sm[];
  float* wsm = sm;                 // [c][h] 128 x 64
  float* ys  = sm + 128 * 64;      // [h][v] 64 x 65 (padded)

  const int u = blockIdx.x, b = blockIdx.y;
  const int tid = threadIdx.x;
  const int p0 = u * 64;

  for (int i = tid; i < 128 * 64; i += 256) wsm[i] = w_out[i];
  for (int i = tid; i < 64 * 64; i += 256) {
    int hh = i >> 6, v = i & 63;
    ys[hh * 65 + v] = y_s[(size_t)(b * HW + hh * 36 + u) * 64 + v];
  }
  __syncthreads();

  const int v4 = (tid & 15) * 4;
  const int c0 = (tid >> 4) * 8;
  float acc[4][8];
#pragma unroll
  for (int i = 0; i < 4; i++)
#pragma unroll
    for (int j = 0; j < 8; j++) acc[i][j] = 0.f;

  for (int h4 = 0; h4 < 64; h4 += 4) {
    float4 wv[8];
#pragma unroll
    for (int j = 0; j < 8; j++)
      wv[j] = *(const float4*)(wsm + (c0 + j) * 64 + h4);
    float yv[4][4];
#pragma unroll
    for (int q = 0; q < 4; q++)
#pragma unroll
      for (int i = 0; i < 4; i++)
        yv[i][q] = ys[(h4 + q) * 65 + v4 + i];
#pragma unroll
    for (int i = 0; i < 4; i++)
#pragma unroll
      for (int j = 0; j < 8; j++) {
        float wa[4] = {wv[j].x, wv[j].y, wv[j].z, wv[j].w};
#pragma unroll
        for (int q = 0; q < 4; q++)
          acc[i][j] = fmaf(yv[i][q], wa[q], acc[i][j]);
      }
  }

#pragma unroll
  for (int i = 0; i < 4; i++) {
    int pix = p0 + v4 + i;
#pragma unroll
    for (int j = 0; j < 8; j++) {
      int c = c0 + j;
      float xi = x[((size_t)(b * CC + c) * TT) * HW + pix];
      out[(size_t)(b * CC + c) * HW + pix] = xi + acc[i][j];
    }
  }
}

// ---------------------------------------------------------------------------
extern "C" void kernel_launch(void* const* d_in, const int* in_sizes, int n_in,
                              void* d_out, int out_size) {
  const float* x       = (const float*)d_in[0];
  const float* w_theta = (const float*)d_in[1];
  const float* w_phi   = (const float*)d_in[2];
  const float* w_g     = (const float*)d_in[3];
  const float* w_out   = (const float*)d_in[4];
  float* out = (float*)d_out;

  const int sm1 = 128 * 132 * 4;                // 67584 B -> 3 CTA/SM
  const int sm3 = (128 * 64 + 64 * 65) * 4;     // 49408 B
  cudaFuncSetAttribute(proj_kernel, cudaFuncAttributeMaxDynamicSharedMemorySize, sm1);
  cudaFuncSetAttribute(outproj_kernel, cudaFuncAttributeMaxDynamicSharedMemorySize, sm3);

  proj_kernel<<<dim3(36, BB, TT), 256, sm1>>>(x, w_theta, w_phi, w_g);
  attn_kernel<<<288, 256>>>();
  outproj_kernel<<<dim3(36, BB), 256, sm3>>>(x, w_out, out);
}

// round 12
// speedup vs baseline: 1.1696x; 1.1696x over previous
#include <cuda_runtime.h>
#include <cuda_bf16.h>

#define BB   2
#define CC   128
#define HCH  64
#define TT   5
#define TC   4
#define HH   48
#define WIW  48
#define HW   2304
#define NKEY 196

// Scratch (device globals; no allocations allowed)
__device__ float theta_s[BB * HW * HCH];                          // [b][p][h] fp32, pre-scaled by 8
__device__ __align__(16) __nv_bfloat16 phi_b[BB * TC * HW * HCH]; // [pix][h] bf16
__device__ __align__(16) __nv_bfloat16 g_b[BB * TC * HW * HCH];   // [pix][slot] bf16, slot(h)=4*(h&15)+(h>>4)
__device__ float y_s[BB * HW * HCH];                              // [b][p][hc]

// packed f32x2 helpers (sm_103a)
#define FMA_F32X2(d, a, b) \
  asm("fma.rn.f32x2 %0, %1, %2, %0;" : "+l"(d) : "l"(a), "l"(b))
#define PACK_F32X2(out, lo, hi) \
  asm("mov.b64 %0, {%1, %2};" : "=l"(out) : "r"(__float_as_uint(lo)), "r"(__float_as_uint(hi)))
#define UNPACK_F32X2(lo, hi, in) \
  do { unsigned _l, _h; asm("mov.b64 {%0, %1}, %2;" : "=r"(_l), "=r"(_h) : "l"(in)); \
       lo = __uint_as_float(_l); hi = __uint_as_float(_h); } while (0)

__device__ __forceinline__ unsigned pack_bf2(float a, float b) {
  __nv_bfloat162 h = __floats2bfloat162_rn(a, b);
  return *(unsigned*)&h;
}

// ---------------------------------------------------------------------------
// Kernel 1: projections (R9 version — xs smem tile + fp32 weights).
// Tile 64px x {64|128}n, 256 threads, grid (36,B,5).
// dyn smem = xs[128c][64px] + wsm[128c][132n] = 99.5KB -> 2 CTA/SM.
// ---------------------------------------------------------------------------
__global__ __launch_bounds__(256) void proj_kernel(
    const float* __restrict__ x,
    const float* __restrict__ w_theta,
    const float* __restrict__ w_phi,
    const float* __restrict__ w_g) {
  extern __shared__ float sm[];
  float* xs  = sm;                 // [c][px] 128 x 64
  float* wsm = sm + 128 * 64;      // [c][n]  128 x 132 (padded)

  const int tile = blockIdx.x, b = blockIdx.y, t = blockIdx.z;
  const int tid = threadIdx.x;
  const int p0 = tile * 64;

  for (int i = tid; i < 128 * 64; i += 256) {
    int c = i >> 6, px = i & 63;
    xs[i] = x[((b * CC + c) * TT + t) * HW + p0 + px];
  }
  if (t == 0) {
    for (int i = tid; i < 64 * 128; i += 256) {
      int n = i >> 7, c = i & 127;
      wsm[c * 132 + n] = w_theta[i];
    }
  } else {
    for (int i = tid; i < 128 * 128; i += 256) {
      int n = i >> 7, c = i & 127;
      wsm[c * 132 + n] = (n < 64) ? w_phi[n * 128 + c] : w_g[(n - 64) * 128 + c];
    }
  }
  __syncthreads();

  const int px4 = (tid & 15) * 4;

  if (t == 0) {
    const int n0 = (tid >> 4) * 4;
    unsigned long long acc[4][2];
#pragma unroll
    for (int i = 0; i < 4; i++) { acc[i][0] = 0ull; acc[i][1] = 0ull; }

#pragma unroll 4
    for (int c = 0; c < 128; c++) {
      float4 xv = *(const float4*)(xs + c * 64 + px4);
      ulonglong2 wp = *(const ulonglong2*)(wsm + c * 132 + n0);
      float xa[4] = {xv.x, xv.y, xv.z, xv.w};
      unsigned long long xd[4];
#pragma unroll
      for (int i = 0; i < 4; i++) PACK_F32X2(xd[i], xa[i], xa[i]);
#pragma unroll
      for (int i = 0; i < 4; i++) {
        FMA_F32X2(acc[i][0], xd[i], wp.x);
        FMA_F32X2(acc[i][1], xd[i], wp.y);
      }
    }
#pragma unroll
    for (int i = 0; i < 4; i++) {
      float f0, f1, f2, f3;
      UNPACK_F32X2(f0, f1, acc[i][0]);
      UNPACK_F32X2(f2, f3, acc[i][1]);
      int pix = p0 + px4 + i;
      *(float4*)(theta_s + (size_t)(b * HW + pix) * 64 + n0) =
          make_float4(8.f * f0, 8.f * f1, 8.f * f2, 8.f * f3);
    }
  } else {
    const int n0 = (tid >> 4) * 8;
    unsigned long long acc[4][4];
#pragma unroll
    for (int i = 0; i < 4; i++)
#pragma unroll
      for (int j = 0; j < 4; j++) acc[i][j] = 0ull;

#pragma unroll 4
    for (int c = 0; c < 128; c++) {
      float4 xv = *(const float4*)(xs + c * 64 + px4);
      ulonglong2 wa = *(const ulonglong2*)(wsm + c * 132 + n0);
      ulonglong2 wb = *(const ulonglong2*)(wsm + c * 132 + n0 + 4);
      unsigned long long wp[4] = {wa.x, wa.y, wb.x, wb.y};
      float xa[4] = {xv.x, xv.y, xv.z, xv.w};
      unsigned long long xd[4];
#pragma unroll
      for (int i = 0; i < 4; i++) PACK_F32X2(xd[i], xa[i], xa[i]);
#pragma unroll
      for (int i = 0; i < 4; i++)
#pragma unroll
        for (int j = 0; j < 4; j++) FMA_F32X2(acc[i][j], xd[i], wp[j]);
    }

    const int nn = n0 & 63;
    const size_t rowb = (size_t)((b * TC + (t - 1)) * HW);
#pragma unroll
    for (int i = 0; i < 4; i++) {
      float f[8];
#pragma unroll
      for (int j = 0; j < 4; j++) UNPACK_F32X2(f[2 * j], f[2 * j + 1], acc[i][j]);
      int pix = p0 + px4 + i;
      if (n0 < 64) {
        uint4 s;
        s.x = pack_bf2(f[0], f[1]); s.y = pack_bf2(f[2], f[3]);
        s.z = pack_bf2(f[4], f[5]); s.w = pack_bf2(f[6], f[7]);
        *(uint4*)(phi_b + (rowb + pix) * 64 + nn) = s;
      } else {
        // g: permuted  slot(h) = 4*(h&15) + (h>>4)
        __nv_bfloat16* gd = g_b + (rowb + pix) * 64;
#pragma unroll
        for (int j = 0; j < 8; j++) {
          int hch = nn + j;
          int slot = ((hch & 15) << 2) | (hch >> 4);
          gd[slot] = __float2bfloat16(f[j]);
        }
      }
    }
  }
}

// ---------------------------------------------------------------------------
// Kernel 2: attention. 512 threads = 16 warps = 16 pixels per block, grid 288.
// Warp W: pp = W&7 (pixel pair), h2 = W>>3 (work split). Halves of a warp
// (lane>>4) serve pixels slot = 2*pp + half.
//  phase 0: warp W computes ofs for pixel slot W; zero ysm2 + logits tail.
//  phase 1: pass1 logits, keys split: h2=0 -> it 0..24, h2=1 -> it 25..48.
//  phase 2: softmax (warps with h2==0 only), e-values + rinv to smem.
//  phase 3: pass2 AV: rem-range split by h2 (0..95 / 96..195+tail), weights
//           hoisted per seg w/ carry-SEL, accumulation DIRECT to smem ysm2
//           (bank-permuted, conflict-free, per-h2 copy -> no cross-warp race).
//  phase 4: y = (copy0+copy1)*rinv.
// ---------------------------------------------------------------------------
__device__ __forceinline__ int ysm_perm(int b) {      // bucket -> bank-spread slot
  return ((b & 3) << 4) | (b >> 2);
}

__global__ __launch_bounds__(512, 2) void attn_kernel() {
  __shared__ float logits[16][200];
  __shared__ int   ofs[16][196];
  __shared__ float ysm2[32 * 72];    // row = slot*2 + h2 (stride 72), col = perm(bucket)
  __shared__ float rinvs[16];
  const int tid = threadIdx.x;
  const int W = tid >> 5, lane = tid & 31;
  const int pp = W & 7, h2 = W >> 3;
  const int half = lane >> 4, l = lane & 15;

  // ---- phase 0: per-pixel offsets (warp W -> pixel slot W), zero scratch ----
  {
    const int pidW = blockIdx.x * 16 + W;
    const int bW = pidW / HW, pW = pidW % HW;
    const int pyW = pW / WIW, pxW = pW % WIW;
#pragma unroll
    for (int j = 0; j < 7; j++) {
      int rem = lane + j * 32;
      if (rem < NKEY) {
        int t = rem / 49, r = rem % 49;
        int dy = r / 7, dx = r % 7;
        int yy = min(max(pyW + dy - 3, 0), HH - 1);
        int xx = min(max(pxW + dx - 3, 0), WIW - 1);
        ofs[W][rem] = ((bW * TC + t) * HW + yy * WIW + xx) * 64;
      }
    }
    if (lane < 4) logits[W][196 + lane] = 0.f;
  }
  for (int i = tid; i < 32 * 72; i += 512) ysm2[i] = 0.f;
  __syncthreads();

  // ---- phase 1: logits (key ranges split across h2) ----
  const int slot = pp * 2 + half;
  const int pid = blockIdx.x * 16 + slot;
  const int b = pid / HW, p = pid % HW;
  const int cp = l & 3, kg = l >> 2;

  {
    const float* qp = theta_s + (size_t)(b * HW + p) * 64 + cp * 16;
    float q[16];
#pragma unroll
    for (int j = 0; j < 4; j++) {
      float4 qv = *(const float4*)(qp + j * 4);
      q[j*4+0] = qv.x; q[j*4+1] = qv.y; q[j*4+2] = qv.z; q[j*4+3] = qv.w;
    }
    const int it0 = h2 ? 25 : 0;
    const int it1 = h2 ? 49 : 25;
#pragma unroll 6
    for (int it = it0; it < it1; it++) {
      int k = it * 4 + kg;
      const uint4* ph = (const uint4*)(phi_b + ofs[slot][k]) + cp * 2;
      uint4 A = ph[0], B2 = ph[1];
      unsigned r[8] = {A.x, A.y, A.z, A.w, B2.x, B2.y, B2.z, B2.w};
      float s = 0.f;
#pragma unroll
      for (int w = 0; w < 8; w++) {
        float lo = __uint_as_float(r[w] << 16);
        float hi = __uint_as_float(r[w] & 0xffff0000u);
        s = fmaf(q[2*w], lo, fmaf(q[2*w+1], hi, s));
      }
      s += __shfl_xor_sync(0xffffffffu, s, 1);
      s += __shfl_xor_sync(0xffffffffu, s, 2);
      if (cp == 0) logits[slot][k] = s;
    }
  }
  __syncthreads();

  // ---- phase 2: softmax (h2==0 warps; 16-lane halves, slot as above) ----
  if (h2 == 0) {
    float lv[13], m = -1e30f;
#pragma unroll
    for (int j = 0; j < 13; j++) {
      int idx = l + j * 16;
      lv[j] = (idx < NKEY) ? logits[slot][idx] : -1e30f;
      m = fmaxf(m, lv[j]);
    }
#pragma unroll
    for (int off = 8; off >= 1; off >>= 1)
      m = fmaxf(m, __shfl_xor_sync(0xffffffffu, m, off));
    float ssum = 0.f;
#pragma unroll
    for (int j = 0; j < 13; j++) {
      int idx = l + j * 16;
      if (idx < NKEY) {
        float e = __expf(lv[j] - m);
        logits[slot][idx] = e;
        ssum += e;
      }
    }
#pragma unroll
    for (int off = 8; off >= 1; off >>= 1)
      ssum += __shfl_xor_sync(0xffffffffu, ssum, off);
    if (l == 0) rinvs[slot] = 1.f / ssum;
  }
  __syncthreads();

  // ---- phase 3: pass2 AV into smem ysm2 ----
  {
    const int fl = 4 * l, wl = 3 * l;
    const int sth = 64 - fl;                 // s >= sth -> carry
    const int row = (slot * 2 + h2) * 72;    // this warp's ysm copy row
    const float* lg = logits[slot];

#define AV_SEG(SEG, S0, S1)                                                  \
    {                                                                        \
      float wlo0 = lg[wl + (SEG) + 0],   whi0 = lg[wl + (SEG) + 1];          \
      float wlo1 = lg[wl + (SEG) + 49],  whi1 = lg[wl + (SEG) + 50];         \
      float wlo2 = lg[wl + (SEG) + 98],  whi2 = lg[wl + (SEG) + 99];         \
      float wlo3 = lg[wl + (SEG) + 147], whi3 = lg[wl + (SEG) + 148];        \
      _Pragma("unroll")                                                      \
      for (int s = (S0); s < (S1); s++) {                                    \
        int o = ofs[slot][(SEG) * 64 + s];                                   \
        uint2 v = *(const uint2*)(g_b + o + fl);                             \
        bool hiც = (s >= sth);                                               \
        float w0 = hiც ? whi0 : wlo0;                                        \
        float w1 = hiც ? whi1 : wlo1;                                        \
        float w2 = hiც ? whi2 : wlo2;                                        \
        float w3 = hiც ? whi3 : wlo3;                                        \
        float g0 = __uint_as_float(v.x << 16);                               \
        float g1 = __uint_as_float(v.x & 0xffff0000u);                       \
        float g2 = __uint_as_float(v.y << 16);                               \
        float g3 = __uint_as_float(v.y & 0xffff0000u);                       \
        float tmp = fmaf(w0, g0, fmaf(w1, g1, fmaf(w2, g2, w3 * g3)));       \
        int pb = ysm_perm((fl + s) & 63);                                    \
        ysm2[row + pb] += tmp;                                               \
      }                                                                      \
    }

    if (h2 == 0) {
      AV_SEG(0, 0, 64);
      AV_SEG(1, 0, 32);
    } else {
      AV_SEG(1, 32, 64);
      AV_SEG(2, 0, 64);
      AV_SEG(3, 0, 4);
    }
#undef AV_SEG
  }
  __syncthreads();

  // ---- phase 4: write y (warp W -> pixel slot W) ----
  {
    const int pidW = blockIdx.x * 16 + W;
    const int bW = pidW / HW, pW = pidW % HW;
    const float ri = rinvs[W];
    const int r0 = (W * 2) * 72, r1 = (W * 2 + 1) * 72;
    int hc0 = lane * 2;
    float v0 = (ysm2[r0 + ysm_perm(hc0)]     + ysm2[r1 + ysm_perm(hc0)])     * ri;
    float v1 = (ysm2[r0 + ysm_perm(hc0 + 1)] + ysm2[r1 + ysm_perm(hc0 + 1)]) * ri;
    *(float2*)(y_s + (size_t)(bW * HW + pW) * 64 + hc0) = make_float2(v0, v1);
  }
}

// ---------------------------------------------------------------------------
// Kernel 3 (raw-reshape of Y[B,HW,64] to [B,64,1,48,48]):
// with pix = u*64+v:  out[b][c][pix] = x[b][c][0][pix]
//                     + sum_h w_out[c][h] * Y[b][h*36 + u][v]
// ---------------------------------------------------------------------------
__global__ __launch_bounds__(256) void outproj_kernel(
    const float* __restrict__ x,
    const float* __restrict__ w_out,
    float* __restrict__ out) {
  extern __shared__ float sm[];
  float* wsm = sm;                 // [c][h] 128 x 64
  float* ys  = sm + 128 * 64;      // [h][v] 64 x 65 (padded)

  const int u = blockIdx.x, b = blockIdx.y;
  const int tid = threadIdx.x;
  const int p0 = u * 64;

  for (int i = tid; i < 128 * 64; i += 256) wsm[i] = w_out[i];
  for (int i = tid; i < 64 * 64; i += 256) {
    int hh = i >> 6, v = i & 63;
    ys[hh * 65 + v] = y_s[(size_t)(b * HW + hh * 36 + u) * 64 + v];
  }
  __syncthreads();

  const int v4 = (tid & 15) * 4;
  const int c0 = (tid >> 4) * 8;
  float acc[4][8];
#pragma unroll
  for (int i = 0; i < 4; i++)
#pragma unroll
    for (int j = 0; j < 8; j++) acc[i][j] = 0.f;

  for (int h4 = 0; h4 < 64; h4 += 4) {
    float4 wv[8];
#pragma unroll
    for (int j = 0; j < 8; j++)
      wv[j] = *(const float4*)(wsm + (c0 + j) * 64 + h4);
    float yv[4][4];
#pragma unroll
    for (int q = 0; q < 4; q++)
#pragma unroll
      for (int i = 0; i < 4; i++)
        yv[i][q] = ys[(h4 + q) * 65 + v4 + i];
#pragma unroll
    for (int i = 0; i < 4; i++)
#pragma unroll
      for (int j = 0; j < 8; j++) {
        float wa[4] = {wv[j].x, wv[j].y, wv[j].z, wv[j].w};
#pragma unroll
        for (int q = 0; q < 4; q++)
          acc[i][j] = fmaf(yv[i][q], wa[q], acc[i][j]);
      }
  }

#pragma unroll
  for (int i = 0; i < 4; i++) {
    int pix = p0 + v4 + i;
#pragma unroll
    for (int j = 0; j < 8; j++) {
      int c = c0 + j;
      float xi = x[((size_t)(b * CC + c) * TT) * HW + pix];
      out[(size_t)(b * CC + c) * HW + pix] = xi + acc[i][j];
    }
  }
}

// ---------------------------------------------------------------------------
extern "C" void kernel_launch(void* const* d_in, const int* in_sizes, int n_in,
                              void* d_out, int out_size) {
  const float* x       = (const float*)d_in[0];
  const float* w_theta = (const float*)d_in[1];
  const float* w_phi   = (const float*)d_in[2];
  const float* w_g     = (const float*)d_in[3];
  const float* w_out   = (const float*)d_in[4];
  float* out = (float*)d_out;

  const int sm1 = (128 * 64 + 128 * 132) * 4;   // 99.5 KB -> 2 CTA/SM
  const int sm3 = (128 * 64 + 64 * 65) * 4;     // 49408 B
  cudaFuncSetAttribute(proj_kernel, cudaFuncAttributeMaxDynamicSharedMemorySize, sm1);
  cudaFuncSetAttribute(outproj_kernel, cudaFuncAttributeMaxDynamicSharedMemorySize, sm3);

  proj_kernel<<<dim3(36, BB, TT), 256, sm1>>>(x, w_theta, w_phi, w_g);
  attn_kernel<<<288, 512>>>();
  outproj_kernel<<<dim3(36, BB), 256, sm3>>>(x, w_out, out);
}

// round 13
// speedup vs baseline: 1.1937x; 1.0206x over previous
#include <cuda_runtime.h>
#include <cuda_bf16.h>

#define BB   2
#define CC   128
#define HCH  64
#define TT   5
#define TC   4
#define HH   48
#define WIW  48
#define HW   2304
#define NKEY 196

// Scratch (device globals; no allocations allowed)
__device__ float theta_s[BB * HW * HCH];                          // [b][p][h] fp32, pre-scaled by 8
__device__ __align__(16) __nv_bfloat16 phi_b[BB * TC * HW * HCH]; // [pix][h] bf16
__device__ __align__(16) __nv_bfloat16 g_b[BB * TC * HW * HCH];   // [pix][slot] bf16, slot(h)=4*(h&15)+(h>>4)
__device__ float y_s[BB * HW * HCH];                              // [b][p][hc]

// packed f32x2 helpers (sm_103a)
#define FMA_F32X2(d, a, b) \
  asm("fma.rn.f32x2 %0, %1, %2, %0;" : "+l"(d) : "l"(a), "l"(b))
#define PACK_F32X2(out, lo, hi) \
  asm("mov.b64 %0, {%1, %2};" : "=l"(out) : "r"(__float_as_uint(lo)), "r"(__float_as_uint(hi)))
#define UNPACK_F32X2(lo, hi, in) \
  do { unsigned _l, _h; asm("mov.b64 {%0, %1}, %2;" : "=r"(_l), "=r"(_h) : "l"(in)); \
       lo = __uint_as_float(_l); hi = __uint_as_float(_h); } while (0)

__device__ __forceinline__ unsigned pack_bf2(float a, float b) {
  __nv_bfloat162 h = __floats2bfloat162_rn(a, b);
  return *(unsigned*)&h;
}

// bf16x2 (even,odd) -> f32x2 (even,odd)
__device__ __forceinline__ unsigned long long bf2_to_f32x2(unsigned r) {
  unsigned long long d;
  asm("mov.b64 %0, {%1, %2};" : "=l"(d)
      : "r"(r << 16), "r"(r & 0xffff0000u));
  return d;
}

#define WPAD 136   // bf16 row pad: 272B rows, 16B-aligned

// ---------------------------------------------------------------------------
// Kernel 1: projections. Tile 64px, 256 threads, grid (36,B,5).
// xs fp32 in smem (32KB) + weights bf16 in smem (34KB) = 66KB -> 3 CTA/SM,
// grid 360 <= 444 slots -> single wave, 24 warps/SM.
// t=0: theta (fp32 out). t>0: warps 0-3 phi (contiguous), warps 4-7 g
// (slot-contiguous channel assignment -> single uint4 store, permute-free).
// ---------------------------------------------------------------------------
__global__ __launch_bounds__(256, 3) void proj_kernel(
    const float* __restrict__ x,
    const float* __restrict__ w_theta,
    const float* __restrict__ w_phi,
    const float* __restrict__ w_g) {
  extern __shared__ float sm[];
  float* xs = sm;                                     // [c][px] 128 x 64 fp32
  __nv_bfloat16* wsm = (__nv_bfloat16*)(sm + 128 * 64);  // [c][WPAD] bf16

  const int tile = blockIdx.x, b = blockIdx.y, t = blockIdx.z;
  const int tid = threadIdx.x;
  const int p0 = tile * 64;

  for (int i = tid; i < 128 * 64; i += 256) {
    int c = i >> 6, px = i & 63;
    xs[i] = x[((b * CC + c) * TT + t) * HW + p0 + px];
  }
  if (t == 0) {
    for (int i = tid; i < 64 * 128; i += 256) {
      int n = i >> 7, c = i & 127;
      wsm[c * WPAD + n] = __float2bfloat16(w_theta[i]);
    }
  } else {
    for (int i = tid; i < 128 * 128; i += 256) {
      int n = i >> 7, c = i & 127;
      float wv = (n < 64) ? w_phi[n * 128 + c] : w_g[(n - 64) * 128 + c];
      wsm[c * WPAD + n] = __float2bfloat16(wv);
    }
  }
  __syncthreads();

  const int px4 = (tid & 15) * 4;
  const int ng = tid >> 4;

  if (t == 0) {
    const int n0 = ng * 4;
    unsigned long long acc[4][2];
#pragma unroll
    for (int i = 0; i < 4; i++) { acc[i][0] = 0ull; acc[i][1] = 0ull; }

#pragma unroll 4
    for (int c = 0; c < 128; c++) {
      float4 xv = *(const float4*)(xs + c * 64 + px4);
      uint2 wr = *(const uint2*)(wsm + c * WPAD + n0);
      unsigned long long wd0 = bf2_to_f32x2(wr.x);
      unsigned long long wd1 = bf2_to_f32x2(wr.y);
      float xa[4] = {xv.x, xv.y, xv.z, xv.w};
      unsigned long long xd[4];
#pragma unroll
      for (int i = 0; i < 4; i++) PACK_F32X2(xd[i], xa[i], xa[i]);
#pragma unroll
      for (int i = 0; i < 4; i++) {
        FMA_F32X2(acc[i][0], xd[i], wd0);
        FMA_F32X2(acc[i][1], xd[i], wd1);
      }
    }
#pragma unroll
    for (int i = 0; i < 4; i++) {
      float f0, f1, f2, f3;
      UNPACK_F32X2(f0, f1, acc[i][0]);
      UNPACK_F32X2(f2, f3, acc[i][1]);
      int pix = p0 + px4 + i;
      *(float4*)(theta_s + (size_t)(b * HW + pix) * 64 + n0) =
          make_float4(8.f * f0, 8.f * f1, 8.f * f2, 8.f * f3);
    }
  } else if (ng < 8) {
    // phi: channels n0..n0+7 contiguous
    const int n0 = ng * 8;
    unsigned long long acc[4][4];
#pragma unroll
    for (int i = 0; i < 4; i++)
#pragma unroll
      for (int j = 0; j < 4; j++) acc[i][j] = 0ull;

#pragma unroll 4
    for (int c = 0; c < 128; c++) {
      float4 xv = *(const float4*)(xs + c * 64 + px4);
      uint4 wr = *(const uint4*)(wsm + c * WPAD + n0);
      unsigned long long wd[4] = {bf2_to_f32x2(wr.x), bf2_to_f32x2(wr.y),
                                  bf2_to_f32x2(wr.z), bf2_to_f32x2(wr.w)};
      float xa[4] = {xv.x, xv.y, xv.z, xv.w};
      unsigned long long xd[4];
#pragma unroll
      for (int i = 0; i < 4; i++) PACK_F32X2(xd[i], xa[i], xa[i]);
#pragma unroll
      for (int i = 0; i < 4; i++)
#pragma unroll
        for (int j = 0; j < 4; j++) FMA_F32X2(acc[i][j], xd[i], wd[j]);
    }

    const size_t rowb = (size_t)((b * TC + (t - 1)) * HW);
#pragma unroll
    for (int i = 0; i < 4; i++) {
      float f[8];
#pragma unroll
      for (int j = 0; j < 4; j++) UNPACK_F32X2(f[2 * j], f[2 * j + 1], acc[i][j]);
      int pix = p0 + px4 + i;
      uint4 s;
      s.x = pack_bf2(f[0], f[1]); s.y = pack_bf2(f[2], f[3]);
      s.z = pack_bf2(f[4], f[5]); s.w = pack_bf2(f[6], f[7]);
      *(uint4*)(phi_b + (rowb + pix) * 64 + n0) = s;
    }
  } else {
    // g: slot-contiguous assignment. s0 = slot base; channels {16m+v, 16m+v+1}
    const int s0 = (ng - 8) * 8;
    const int v = (ng - 8) * 2;
    unsigned long long acc[4][4];   // acc[i][m] = channels (16m+v, 16m+v+1)
#pragma unroll
    for (int i = 0; i < 4; i++)
#pragma unroll
      for (int j = 0; j < 4; j++) acc[i][j] = 0ull;

#pragma unroll 4
    for (int c = 0; c < 128; c++) {
      float4 xv = *(const float4*)(xs + c * 64 + px4);
      unsigned long long wd[4];
#pragma unroll
      for (int m = 0; m < 4; m++) {
        unsigned wr = *(const unsigned*)(wsm + c * WPAD + 64 + v + 16 * m);
        wd[m] = bf2_to_f32x2(wr);
      }
      float xa[4] = {xv.x, xv.y, xv.z, xv.w};
      unsigned long long xd[4];
#pragma unroll
      for (int i = 0; i < 4; i++) PACK_F32X2(xd[i], xa[i], xa[i]);
#pragma unroll
      for (int i = 0; i < 4; i++)
#pragma unroll
        for (int m = 0; m < 4; m++) FMA_F32X2(acc[i][m], xd[i], wd[m]);
    }

    const size_t rowb = (size_t)((b * TC + (t - 1)) * HW);
#pragma unroll
    for (int i = 0; i < 4; i++) {
      float lo[4], hi[4];
#pragma unroll
      for (int m = 0; m < 4; m++) UNPACK_F32X2(lo[m], hi[m], acc[i][m]);
      int pix = p0 + px4 + i;
      uint4 s;                               // slots s0..s0+7
      s.x = pack_bf2(lo[0], lo[1]);          // s0+0, s0+1
      s.y = pack_bf2(lo[2], lo[3]);          // s0+2, s0+3
      s.z = pack_bf2(hi[0], hi[1]);          // s0+4, s0+5
      s.w = pack_bf2(hi[2], hi[3]);          // s0+6, s0+7
      *(uint4*)(g_b + (rowb + pix) * 64 + s0) = s;
    }
  }
}

// ---------------------------------------------------------------------------
// Kernel 2: attention. 512 threads = 16 warps = 16 pixels per block, grid 288.
// (unchanged from R12 — validated at ~30us)
// ---------------------------------------------------------------------------
__device__ __forceinline__ int ysm_perm(int b) {      // bucket -> bank-spread slot
  return ((b & 3) << 4) | (b >> 2);
}

__global__ __launch_bounds__(512, 2) void attn_kernel() {
  __shared__ float logits[16][200];
  __shared__ int   ofs[16][196];
  __shared__ float ysm2[32 * 72];    // row = slot*2 + h2 (stride 72), col = perm(bucket)
  __shared__ float rinvs[16];
  const int tid = threadIdx.x;
  const int W = tid >> 5, lane = tid & 31;
  const int pp = W & 7, h2 = W >> 3;
  const int half = lane >> 4, l = lane & 15;

  // ---- phase 0: per-pixel offsets (warp W -> pixel slot W), zero scratch ----
  {
    const int pidW = blockIdx.x * 16 + W;
    const int bW = pidW / HW, pW = pidW % HW;
    const int pyW = pW / WIW, pxW = pW % WIW;
#pragma unroll
    for (int j = 0; j < 7; j++) {
      int rem = lane + j * 32;
      if (rem < NKEY) {
        int t = rem / 49, r = rem % 49;
        int dy = r / 7, dx = r % 7;
        int yy = min(max(pyW + dy - 3, 0), HH - 1);
        int xx = min(max(pxW + dx - 3, 0), WIW - 1);
        ofs[W][rem] = ((bW * TC + t) * HW + yy * WIW + xx) * 64;
      }
    }
    if (lane < 4) logits[W][196 + lane] = 0.f;
  }
  for (int i = tid; i < 32 * 72; i += 512) ysm2[i] = 0.f;
  __syncthreads();

  // ---- phase 1: logits (key ranges split across h2) ----
  const int slot = pp * 2 + half;
  const int pid = blockIdx.x * 16 + slot;
  const int b = pid / HW, p = pid % HW;
  const int cp = l & 3, kg = l >> 2;

  {
    const float* qp = theta_s + (size_t)(b * HW + p) * 64 + cp * 16;
    float q[16];
#pragma unroll
    for (int j = 0; j < 4; j++) {
      float4 qv = *(const float4*)(qp + j * 4);
      q[j*4+0] = qv.x; q[j*4+1] = qv.y; q[j*4+2] = qv.z; q[j*4+3] = qv.w;
    }
    const int it0 = h2 ? 25 : 0;
    const int it1 = h2 ? 49 : 25;
#pragma unroll 6
    for (int it = it0; it < it1; it++) {
      int k = it * 4 + kg;
      const uint4* ph = (const uint4*)(phi_b + ofs[slot][k]) + cp * 2;
      uint4 A = ph[0], B2 = ph[1];
      unsigned r[8] = {A.x, A.y, A.z, A.w, B2.x, B2.y, B2.z, B2.w};
      float s = 0.f;
#pragma unroll
      for (int w = 0; w < 8; w++) {
        float lo = __uint_as_float(r[w] << 16);
        float hi = __uint_as_float(r[w] & 0xffff0000u);
        s = fmaf(q[2*w], lo, fmaf(q[2*w+1], hi, s));
      }
      s += __shfl_xor_sync(0xffffffffu, s, 1);
      s += __shfl_xor_sync(0xffffffffu, s, 2);
      if (cp == 0) logits[slot][k] = s;
    }
  }
  __syncthreads();

  // ---- phase 2: softmax (h2==0 warps; 16-lane halves) ----
  if (h2 == 0) {
    float lv[13], m = -1e30f;
#pragma unroll
    for (int j = 0; j < 13; j++) {
      int idx = l + j * 16;
      lv[j] = (idx < NKEY) ? logits[slot][idx] : -1e30f;
      m = fmaxf(m, lv[j]);
    }
#pragma unroll
    for (int off = 8; off >= 1; off >>= 1)
      m = fmaxf(m, __shfl_xor_sync(0xffffffffu, m, off));
    float ssum = 0.f;
#pragma unroll
    for (int j = 0; j < 13; j++) {
      int idx = l + j * 16;
      if (idx < NKEY) {
        float e = __expf(lv[j] - m);
        logits[slot][idx] = e;
        ssum += e;
      }
    }
#pragma unroll
    for (int off = 8; off >= 1; off >>= 1)
      ssum += __shfl_xor_sync(0xffffffffu, ssum, off);
    if (l == 0) rinvs[slot] = 1.f / ssum;
  }
  __syncthreads();

  // ---- phase 3: pass2 AV into smem ysm2 ----
  {
    const int fl = 4 * l, wl = 3 * l;
    const int sth = 64 - fl;                 // s >= sth -> carry
    const int row = (slot * 2 + h2) * 72;    // this warp's ysm copy row
    const float* lg = logits[slot];

#define AV_SEG(SEG, S0, S1)                                                  \
    {                                                                        \
      float wlo0 = lg[wl + (SEG) + 0],   whi0 = lg[wl + (SEG) + 1];          \
      float wlo1 = lg[wl + (SEG) + 49],  whi1 = lg[wl + (SEG) + 50];         \
      float wlo2 = lg[wl + (SEG) + 98],  whi2 = lg[wl + (SEG) + 99];         \
      float wlo3 = lg[wl + (SEG) + 147], whi3 = lg[wl + (SEG) + 148];        \
      _Pragma("unroll")                                                      \
      for (int s = (S0); s < (S1); s++) {                                    \
        int o = ofs[slot][(SEG) * 64 + s];                                   \
        uint2 v = *(const uint2*)(g_b + o + fl);                             \
        bool hic = (s >= sth);                                               \
        float w0 = hic ? whi0 : wlo0;                                        \
        float w1 = hic ? whi1 : wlo1;                                        \
        float w2 = hic ? whi2 : wlo2;                                        \
        float w3 = hic ? whi3 : wlo3;                                        \
        float g0 = __uint_as_float(v.x << 16);                               \
        float g1 = __uint_as_float(v.x & 0xffff0000u);                       \
        float g2 = __uint_as_float(v.y << 16);                               \
        float g3 = __uint_as_float(v.y & 0xffff0000u);                       \
        float tmp = fmaf(w0, g0, fmaf(w1, g1, fmaf(w2, g2, w3 * g3)));       \
        int pb = ysm_perm((fl + s) & 63);                                    \
        ysm2[row + pb] += tmp;                                               \
      }                                                                      \
    }

    if (h2 == 0) {
      AV_SEG(0, 0, 64);
      AV_SEG(1, 0, 32);
    } else {
      AV_SEG(1, 32, 64);
      AV_SEG(2, 0, 64);
      AV_SEG(3, 0, 4);
    }
#undef AV_SEG
  }
  __syncthreads();

  // ---- phase 4: write y (warp W -> pixel slot W) ----
  {
    const int pidW = blockIdx.x * 16 + W;
    const int bW = pidW / HW, pW = pidW % HW;
    const float ri = rinvs[W];
    const int r0 = (W * 2) * 72, r1 = (W * 2 + 1) * 72;
    int hc0 = lane * 2;
    float v0 = (ysm2[r0 + ysm_perm(hc0)]     + ysm2[r1 + ysm_perm(hc0)])     * ri;
    float v1 = (ysm2[r0 + ysm_perm(hc0 + 1)] + ysm2[r1 + ysm_perm(hc0 + 1)]) * ri;
    *(float2*)(y_s + (size_t)(bW * HW + pW) * 64 + hc0) = make_float2(v0, v1);
  }
}

// ---------------------------------------------------------------------------
// Kernel 3 (raw-reshape of Y[B,HW,64] to [B,64,1,48,48]):
// with pix = u*64+v:  out[b][c][pix] = x[b][c][0][pix]
//                     + sum_h w_out[c][h] * Y[b][h*36 + u][v]
// ---------------------------------------------------------------------------
__global__ __launch_bounds__(256) void outproj_kernel(
    const float* __restrict__ x,
    const float* __restrict__ w_out,
    float* __restrict__ out) {
  extern __shared__ float sm[];
  float* wsm = sm;                 // [c][h] 128 x 64
  float* ys  = sm + 128 * 64;      // [h][v] 64 x 65 (padded)

  const int u = blockIdx.x, b = blockIdx.y;
  const int tid = threadIdx.x;
  const int p0 = u * 64;

  for (int i = tid; i < 128 * 64; i += 256) wsm[i] = w_out[i];
  for (int i = tid; i < 64 * 64; i += 256) {
    int hh = i >> 6, v = i & 63;
    ys[hh * 65 + v] = y_s[(size_t)(b * HW + hh * 36 + u) * 64 + v];
  }
  __syncthreads();

  const int v4 = (tid & 15) * 4;
  const int c0 = (tid >> 4) * 8;
  float acc[4][8];
#pragma unroll
  for (int i = 0; i < 4; i++)
#pragma unroll
    for (int j = 0; j < 8; j++) acc[i][j] = 0.f;

  for (int h4 = 0; h4 < 64; h4 += 4) {
    float4 wv[8];
#pragma unroll
    for (int j = 0; j < 8; j++)
      wv[j] = *(const float4*)(wsm + (c0 + j) * 64 + h4);
    float yv[4][4];
#pragma unroll
    for (int q = 0; q < 4; q++)
#pragma unroll
      for (int i = 0; i < 4; i++)
        yv[i][q] = ys[(h4 + q) * 65 + v4 + i];
#pragma unroll
    for (int i = 0; i < 4; i++)
#pragma unroll
      for (int j = 0; j < 8; j++) {
        float wa[4] = {wv[j].x, wv[j].y, wv[j].z, wv[j].w};
#pragma unroll
        for (int q = 0; q < 4; q++)
          acc[i][j] = fmaf(yv[i][q], wa[q], acc[i][j]);
      }
  }

#pragma unroll
  for (int i = 0; i < 4; i++) {
    int pix = p0 + v4 + i;
#pragma unroll
    for (int j = 0; j < 8; j++) {
      int c = c0 + j;
      float xi = x[((size_t)(b * CC + c) * TT) * HW + pix];
      out[(size_t)(b * CC + c) * HW + pix] = xi + acc[i][j];
    }
  }
}

// ---------------------------------------------------------------------------
extern "C" void kernel_launch(void* const* d_in, const int* in_sizes, int n_in,
                              void* d_out, int out_size) {
  const float* x       = (const float*)d_in[0];
  const float* w_theta = (const float*)d_in[1];
  const float* w_phi   = (const float*)d_in[2];
  const float* w_g     = (const float*)d_in[3];
  const float* w_out   = (const float*)d_in[4];
  float* out = (float*)d_out;

  const int sm1 = 128 * 64 * 4 + 128 * WPAD * 2;  // 32768 + 34816 = 67584 B -> 3 CTA/SM
  const int sm3 = (128 * 64 + 64 * 65) * 4;       // 49408 B
  cudaFuncSetAttribute(proj_kernel, cudaFuncAttributeMaxDynamicSharedMemorySize, sm1);
  cudaFuncSetAttribute(outproj_kernel, cudaFuncAttributeMaxDynamicSharedMemorySize, sm3);

  proj_kernel<<<dim3(36, BB, TT), 256, sm1>>>(x, w_theta, w_phi, w_g);
  attn_kernel<<<288, 512>>>();
  outproj_kernel<<<dim3(36, BB), 256, sm3>>>(x, w_out, out);
}

// round 15
// speedup vs baseline: 1.2177x; 1.0201x over previous
#include <cuda_runtime.h>
#include <cuda_bf16.h>

#define BB   2
#define CC   128
#define HCH  64
#define TT   5
#define TC   4
#define HH   48
#define WIW  48
#define HW   2304
#define NKEY 196

// Scratch (device globals; no allocations allowed)
__device__ float theta_s[BB * HW * HCH];                          // [b][p][h] fp32, pre-scaled by 8
__device__ __align__(16) __nv_bfloat16 phi_b[BB * TC * HW * HCH]; // [pix][h] bf16
__device__ __align__(16) __nv_bfloat16 g_b[BB * TC * HW * HCH];   // [pix][slot] bf16, slot(h)=4*(h&15)+(h>>4)
__device__ float y_s[BB * HW * HCH];                              // [b][p][hc]

// packed f32x2 helpers (sm_103a)
#define FMA_F32X2(d, a, b) \
  asm("fma.rn.f32x2 %0, %1, %2, %0;" : "+l"(d) : "l"(a), "l"(b))
#define PACK_F32X2(out, lo, hi) \
  asm("mov.b64 %0, {%1, %2};" : "=l"(out) : "r"(__float_as_uint(lo)), "r"(__float_as_uint(hi)))
#define UNPACK_F32X2(lo, hi, in) \
  do { unsigned _l, _h; asm("mov.b64 {%0, %1}, %2;" : "=r"(_l), "=r"(_h) : "l"(in)); \
       lo = __uint_as_float(_l); hi = __uint_as_float(_h); } while (0)

__device__ __forceinline__ unsigned pack_bf2(float a, float b) {
  __nv_bfloat162 h = __floats2bfloat162_rn(a, b);
  return *(unsigned*)&h;
}

// bf16x2 (even,odd) -> f32x2 (even,odd)
__device__ __forceinline__ unsigned long long bf2_to_f32x2(unsigned r) {
  unsigned long long d;
  asm("mov.b64 %0, {%1, %2};" : "=l"(d)
      : "r"(r << 16), "r"(r & 0xffff0000u));
  return d;
}

#define WPAD 136   // bf16 weight row pad: 272B rows, 16B-aligned

// ---------------------------------------------------------------------------
// Kernel 1: projections. Tile 64px, 256 threads, grid (36,B,5).
// xs bf16 (16KB) + weights bf16 (34KB) = 50KB -> 4 CTA/SM, 32 warps/SM,
// grid 360 <= 592 slots -> single wave.
// t=0: theta (fp32 out). t>0: warps 0-3 phi (contiguous), warps 4-7 g
// (slot-contiguous channel assignment -> single uint4 store, permute-free).
// ---------------------------------------------------------------------------
__global__ __launch_bounds__(256, 4) void proj_kernel(
    const float* __restrict__ x,
    const float* __restrict__ w_theta,
    const float* __restrict__ w_phi,
    const float* __restrict__ w_g) {
  extern __shared__ __nv_bfloat16 smb[];
  __nv_bfloat16* xs  = smb;                 // [c][px] 128 x 64 bf16
  __nv_bfloat16* wsm = smb + 128 * 64;      // [c][WPAD] bf16

  const int tile = blockIdx.x, b = blockIdx.y, t = blockIdx.z;
  const int tid = threadIdx.x;
  const int p0 = tile * 64;

  // stage x as bf16 (2 px per thread-iter, coalesced LDG.64 / STS.32)
  for (int i = tid; i < 128 * 32; i += 256) {
    int c = i >> 5, pxp = (i & 31) * 2;
    float2 v = *(const float2*)(x + ((size_t)(b * CC + c) * TT + t) * HW + p0 + pxp);
    *(unsigned*)(xs + c * 64 + pxp) = pack_bf2(v.x, v.y);
  }
  if (t == 0) {
    for (int i = tid; i < 64 * 128; i += 256) {
      int n = i >> 7, c = i & 127;
      wsm[c * WPAD + n] = __float2bfloat16(w_theta[i]);
    }
  } else {
    for (int i = tid; i < 128 * 128; i += 256) {
      int n = i >> 7, c = i & 127;
      float wv = (n < 64) ? w_phi[n * 128 + c] : w_g[(n - 64) * 128 + c];
      wsm[c * WPAD + n] = __float2bfloat16(wv);
    }
  }
  __syncthreads();

  const int px4 = (tid & 15) * 4;
  const int ng = tid >> 4;

  if (t == 0) {
    const int n0 = ng * 4;
    unsigned long long acc[4][2];
#pragma unroll
    for (int i = 0; i < 4; i++) { acc[i][0] = 0ull; acc[i][1] = 0ull; }

#pragma unroll 4
    for (int c = 0; c < 128; c++) {
      uint2 xr = *(const uint2*)(xs + c * 64 + px4);     // 4 px bf16
      uint2 wr = *(const uint2*)(wsm + c * WPAD + n0);   // 4 n bf16
      unsigned long long wd0 = bf2_to_f32x2(wr.x);
      unsigned long long wd1 = bf2_to_f32x2(wr.y);
      float xa[4];
      xa[0] = __uint_as_float(xr.x << 16);
      xa[1] = __uint_as_float(xr.x & 0xffff0000u);
      xa[2] = __uint_as_float(xr.y << 16);
      xa[3] = __uint_as_float(xr.y & 0xffff0000u);
      unsigned long long xd[4];
#pragma unroll
      for (int i = 0; i < 4; i++) PACK_F32X2(xd[i], xa[i], xa[i]);
#pragma unroll
      for (int i = 0; i < 4; i++) {
        FMA_F32X2(acc[i][0], xd[i], wd0);
        FMA_F32X2(acc[i][1], xd[i], wd1);
      }
    }
#pragma unroll
    for (int i = 0; i < 4; i++) {
      float f0, f1, f2, f3;
      UNPACK_F32X2(f0, f1, acc[i][0]);
      UNPACK_F32X2(f2, f3, acc[i][1]);
      int pix = p0 + px4 + i;
      *(float4*)(theta_s + (size_t)(b * HW + pix) * 64 + n0) =
          make_float4(8.f * f0, 8.f * f1, 8.f * f2, 8.f * f3);
    }
  } else if (ng < 8) {
    // phi: channels n0..n0+7 contiguous
    const int n0 = ng * 8;
    unsigned long long acc[4][4];
#pragma unroll
    for (int i = 0; i < 4; i++)
#pragma unroll
      for (int j = 0; j < 4; j++) acc[i][j] = 0ull;

#pragma unroll 4
    for (int c = 0; c < 128; c++) {
      uint2 xr = *(const uint2*)(xs + c * 64 + px4);
      uint4 wr = *(const uint4*)(wsm + c * WPAD + n0);
      unsigned long long wd[4] = {bf2_to_f32x2(wr.x), bf2_to_f32x2(wr.y),
                                  bf2_to_f32x2(wr.z), bf2_to_f32x2(wr.w)};
      float xa[4];
      xa[0] = __uint_as_float(xr.x << 16);
      xa[1] = __uint_as_float(xr.x & 0xffff0000u);
      xa[2] = __uint_as_float(xr.y << 16);
      xa[3] = __uint_as_float(xr.y & 0xffff0000u);
      unsigned long long xd[4];
#pragma unroll
      for (int i = 0; i < 4; i++) PACK_F32X2(xd[i], xa[i], xa[i]);
#pragma unroll
      for (int i = 0; i < 4; i++)
#pragma unroll
        for (int j = 0; j < 4; j++) FMA_F32X2(acc[i][j], xd[i], wd[j]);
    }

    const size_t rowb = (size_t)((b * TC + (t - 1)) * HW);
#pragma unroll
    for (int i = 0; i < 4; i++) {
      float f[8];
#pragma unroll
      for (int j = 0; j < 4; j++) UNPACK_F32X2(f[2 * j], f[2 * j + 1], acc[i][j]);
      int pix = p0 + px4 + i;
      uint4 s;
      s.x = pack_bf2(f[0], f[1]); s.y = pack_bf2(f[2], f[3]);
      s.z = pack_bf2(f[4], f[5]); s.w = pack_bf2(f[6], f[7]);
      *(uint4*)(phi_b + (rowb + pix) * 64 + n0) = s;
    }
  } else {
    // g: slot-contiguous assignment. s0 = slot base; channels {16m+v, 16m+v+1}
    const int s0 = (ng - 8) * 8;
    const int v = (ng - 8) * 2;
    unsigned long long acc[4][4];   // acc[i][m] = channels (16m+v, 16m+v+1)
#pragma unroll
    for (int i = 0; i < 4; i++)
#pragma unroll
      for (int j = 0; j < 4; j++) acc[i][j] = 0ull;

#pragma unroll 4
    for (int c = 0; c < 128; c++) {
      uint2 xr = *(const uint2*)(xs + c * 64 + px4);
      unsigned long long wd[4];
#pragma unroll
      for (int m = 0; m < 4; m++) {
        unsigned wr = *(const unsigned*)(wsm + c * WPAD + 64 + v + 16 * m);
        wd[m] = bf2_to_f32x2(wr);
      }
      float xa[4];
      xa[0] = __uint_as_float(xr.x << 16);
      xa[1] = __uint_as_float(xr.x & 0xffff0000u);
      xa[2] = __uint_as_float(xr.y << 16);
      xa[3] = __uint_as_float(xr.y & 0xffff0000u);
      unsigned long long xd[4];
#pragma unroll
      for (int i = 0; i < 4; i++) PACK_F32X2(xd[i], xa[i], xa[i]);
#pragma unroll
      for (int i = 0; i < 4; i++)
#pragma unroll
        for (int m = 0; m < 4; m++) FMA_F32X2(acc[i][m], xd[i], wd[m]);
    }

    const size_t rowb = (size_t)((b * TC + (t - 1)) * HW);
#pragma unroll
    for (int i = 0; i < 4; i++) {
      float lo[4], hi[4];
#pragma unroll
      for (int m = 0; m < 4; m++) UNPACK_F32X2(lo[m], hi[m], acc[i][m]);
      int pix = p0 + px4 + i;
      uint4 s;                               // slots s0..s0+7
      s.x = pack_bf2(lo[0], lo[1]);          // s0+0, s0+1
      s.y = pack_bf2(lo[2], lo[3]);          // s0+2, s0+3
      s.z = pack_bf2(hi[0], hi[1]);          // s0+4, s0+5
      s.w = pack_bf2(hi[2], hi[3]);          // s0+6, s0+7
      *(uint4*)(g_b + (rowb + pix) * 64 + s0) = s;
    }
  }
}

// ---------------------------------------------------------------------------
// Kernel 2: attention. 512 threads = 16 warps = 16 pixels per block, grid 288.
// (unchanged from R12 — validated)
// ---------------------------------------------------------------------------
__device__ __forceinline__ int ysm_perm(int b) {      // bucket -> bank-spread slot
  return ((b & 3) << 4) | (b >> 2);
}

__global__ __launch_bounds__(512, 2) void attn_kernel() {
  __shared__ float logits[16][200];
  __shared__ int   ofs[16][196];
  __shared__ float ysm2[32 * 72];    // row = slot*2 + h2 (stride 72), col = perm(bucket)
  __shared__ float rinvs[16];
  const int tid = threadIdx.x;
  const int W = tid >> 5, lane = tid & 31;
  const int pp = W & 7, h2 = W >> 3;
  const int half = lane >> 4, l = lane & 15;

  // ---- phase 0: per-pixel offsets (warp W -> pixel slot W), zero scratch ----
  {
    const int pidW = blockIdx.x * 16 + W;
    const int bW = pidW / HW, pW = pidW % HW;
    const int pyW = pW / WIW, pxW = pW % WIW;
#pragma unroll
    for (int j = 0; j < 7; j++) {
      int rem = lane + j * 32;
      if (rem < NKEY) {
        int t = rem / 49, r = rem % 49;
        int dy = r / 7, dx = r % 7;
        int yy = min(max(pyW + dy - 3, 0), HH - 1);
        int xx = min(max(pxW + dx - 3, 0), WIW - 1);
        ofs[W][rem] = ((bW * TC + t) * HW + yy * WIW + xx) * 64;
      }
    }
    if (lane < 4) logits[W][196 + lane] = 0.f;
  }
  for (int i = tid; i < 32 * 72; i += 512) ysm2[i] = 0.f;
  __syncthreads();

  // ---- phase 1: logits (key ranges split across h2) ----
  const int slot = pp * 2 + half;
  const int pid = blockIdx.x * 16 + slot;
  const int b = pid / HW, p = pid % HW;
  const int cp = l & 3, kg = l >> 2;

  {
    const float* qp = theta_s + (size_t)(b * HW + p) * 64 + cp * 16;
    float q[16];
#pragma unroll
    for (int j = 0; j < 4; j++) {
      float4 qv = *(const float4*)(qp + j * 4);
      q[j*4+0] = qv.x; q[j*4+1] = qv.y; q[j*4+2] = qv.z; q[j*4+3] = qv.w;
    }
    const int it0 = h2 ? 25 : 0;
    const int it1 = h2 ? 49 : 25;
#pragma unroll 6
    for (int it = it0; it < it1; it++) {
      int k = it * 4 + kg;
      const uint4* ph = (const uint4*)(phi_b + ofs[slot][k]) + cp * 2;
      uint4 A = ph[0], B2 = ph[1];
      unsigned r[8] = {A.x, A.y, A.z, A.w, B2.x, B2.y, B2.z, B2.w};
      float s = 0.f;
#pragma unroll
      for (int w = 0; w < 8; w++) {
        float lo = __uint_as_float(r[w] << 16);
        float hi = __uint_as_float(r[w] & 0xffff0000u);
        s = fmaf(q[2*w], lo, fmaf(q[2*w+1], hi, s));
      }
      s += __shfl_xor_sync(0xffffffffu, s, 1);
      s += __shfl_xor_sync(0xffffffffu, s, 2);
      if (cp == 0) logits[slot][k] = s;
    }
  }
  __syncthreads();

  // ---- phase 2: softmax (h2==0 warps; 16-lane halves) ----
  if (h2 == 0) {
    float lv[13], m = -1e30f;
#pragma unroll
    for (int j = 0; j < 13; j++) {
      int idx = l + j * 16;
      lv[j] = (idx < NKEY) ? logits[slot][idx] : -1e30f;
      m = fmaxf(m, lv[j]);
    }
#pragma unroll
    for (int off = 8; off >= 1; off >>= 1)
      m = fmaxf(m, __shfl_xor_sync(0xffffffffu, m, off));
    float ssum = 0.f;
#pragma unroll
    for (int j = 0; j < 13; j++) {
      int idx = l + j * 16;
      if (idx < NKEY) {
        float e = __expf(lv[j] - m);
        logits[slot][idx] = e;
        ssum += e;
      }
    }
#pragma unroll
    for (int off = 8; off >= 1; off >>= 1)
      ssum += __shfl_xor_sync(0xffffffffu, ssum, off);
    if (l == 0) rinvs[slot] = 1.f / ssum;
  }
  __syncthreads();

  // ---- phase 3: pass2 AV into smem ysm2 ----
  {
    const int fl = 4 * l, wl = 3 * l;
    const int sth = 64 - fl;                 // s >= sth -> carry
    const int row = (slot * 2 + h2) * 72;    // this warp's ysm copy row
    const float* lg = logits[slot];

#define AV_SEG(SEG, S0, S1)                                                  \
    {                                                                        \
      float wlo0 = lg[wl + (SEG) + 0],   whi0 = lg[wl + (SEG) + 1];          \
      float wlo1 = lg[wl + (SEG) + 49],  whi1 = lg[wl + (SEG) + 50];         \
      float wlo2 = lg[wl + (SEG) + 98],  whi2 = lg[wl + (SEG) + 99];         \
      float wlo3 = lg[wl + (SEG) + 147], whi3 = lg[wl + (SEG) + 148];        \
      _Pragma("unroll")                                                      \
      for (int s = (S0); s < (S1); s++) {                                    \
        int o = ofs[slot][(SEG) * 64 + s];                                   \
        uint2 v = *(const uint2*)(g_b + o + fl);                             \
        bool hic = (s >= sth);                                               \
        float w0 = hic ? whi0 : wlo0;                                        \
        float w1 = hic ? whi1 : wlo1;                                        \
        float w2 = hic ? whi2 : wlo2;                                        \
        float w3 = hic ? whi3 : wlo3;                                        \
        float g0 = __uint_as_float(v.x << 16);                               \
        float g1 = __uint_as_float(v.x & 0xffff0000u);                       \
        float g2 = __uint_as_float(v.y << 16);                               \
        float g3 = __uint_as_float(v.y & 0xffff0000u);                       \
        float tmp = fmaf(w0, g0, fmaf(w1, g1, fmaf(w2, g2, w3 * g3)));       \
        int pb = ysm_perm((fl + s) & 63);                                    \
        ysm2[row + pb] += tmp;                                               \
      }                                                                      \
    }

    if (h2 == 0) {
      AV_SEG(0, 0, 64);
      AV_SEG(1, 0, 32);
    } else {
      AV_SEG(1, 32, 64);
      AV_SEG(2, 0, 64);
      AV_SEG(3, 0, 4);
    }
#undef AV_SEG
  }
  __syncthreads();

  // ---- phase 4: write y (warp W -> pixel slot W) ----
  {
    const int pidW = blockIdx.x * 16 + W;
    const int bW = pidW / HW, pW = pidW % HW;
    const float ri = rinvs[W];
    const int r0 = (W * 2) * 72, r1 = (W * 2 + 1) * 72;
    int hc0 = lane * 2;
    float v0 = (ysm2[r0 + ysm_perm(hc0)]     + ysm2[r1 + ysm_perm(hc0)])     * ri;
    float v1 = (ysm2[r0 + ysm_perm(hc0 + 1)] + ysm2[r1 + ysm_perm(hc0 + 1)]) * ri;
    *(float2*)(y_s + (size_t)(bW * HW + pW) * 64 + hc0) = make_float2(v0, v1);
  }
}

// ---------------------------------------------------------------------------
// Kernel 3 (raw-reshape of Y[B,HW,64] to [B,64,1,48,48]):
// with pix = u*64+v:  out[b][c][pix] = x[b][c][0][pix]
//                     + sum_h w_out[c][h] * Y[b][h*36 + u][v]
// ---------------------------------------------------------------------------
__global__ __launch_bounds__(256) void outproj_kernel(
    const float* __restrict__ x,
    const float* __restrict__ w_out,
    float* __restrict__ out) {
  extern __shared__ float sm[];
  float* wsm = sm;                 // [c][h] 128 x 64
  float* ys  = sm + 128 * 64;      // [h][v] 64 x 65 (padded)

  const int u = blockIdx.x, b = blockIdx.y;
  const int tid = threadIdx.x;
  const int p0 = u * 64;

  for (int i = tid; i < 128 * 64; i += 256) wsm[i] = w_out[i];
  for (int i = tid; i < 64 * 64; i += 256) {
    int hh = i >> 6, v = i & 63;
    ys[hh * 65 + v] = y_s[(size_t)(b * HW + hh * 36 + u) * 64 + v];
  }
  __syncthreads();

  const int v4 = (tid & 15) * 4;
  const int c0 = (tid >> 4) * 8;
  float acc[4][8];
#pragma unroll
  for (int i = 0; i < 4; i++)
#pragma unroll
    for (int j = 0; j < 8; j++) acc[i][j] = 0.f;

  for (int h4 = 0; h4 < 64; h4 += 4) {
    float4 wv[8];
#pragma unroll
    for (int j = 0; j < 8; j++)
      wv[j] = *(const float4*)(wsm + (c0 + j) * 64 + h4);
    float yv[4][4];
#pragma unroll
    for (int q = 0; q < 4; q++)
#pragma unroll
      for (int i = 0; i < 4; i++)
        yv[i][q] = ys[(h4 + q) * 65 + v4 + i];
#pragma unroll
    for (int i = 0; i < 4; i++)
#pragma unroll
      for (int j = 0; j < 8; j++) {
        float wa[4] = {wv[j].x, wv[j].y, wv[j].z, wv[j].w};
#pragma unroll
        for (int q = 0; q < 4; q++)
          acc[i][j] = fmaf(yv[i][q], wa[q], acc[i][j]);
      }
  }

#pragma unroll
  for (int i = 0; i < 4; i++) {
    int pix = p0 + v4 + i;
#pragma unroll
    for (int j = 0; j < 8; j++) {
      int c = c0 + j;
      float xi = x[((size_t)(b * CC + c) * TT) * HW + pix];
      out[(size_t)(b * CC + c) * HW + pix] = xi + acc[i][j];
    }
  }
}

// ---------------------------------------------------------------------------
extern "C" void kernel_launch(void* const* d_in, const int* in_sizes, int n_in,
                              void* d_out, int out_size) {
  const float* x       = (const float*)d_in[0];
  const float* w_theta = (const float*)d_in[1];
  const float* w_phi   = (const float*)d_in[2];
  const float* w_g     = (const float*)d_in[3];
  const float* w_out   = (const float*)d_in[4];
  float* out = (float*)d_out;

  const int sm1 = 128 * 64 * 2 + 128 * WPAD * 2;  // 16384 + 34816 = 51200 B -> 4 CTA/SM
  const int sm3 = (128 * 64 + 64 * 65) * 4;       // 49408 B
  cudaFuncSetAttribute(proj_kernel, cudaFuncAttributeMaxDynamicSharedMemorySize, sm1);
  cudaFuncSetAttribute(outproj_kernel, cudaFuncAttributeMaxDynamicSharedMemorySize, sm3);

  proj_kernel<<<dim3(36, BB, TT), 256, sm1>>>(x, w_theta, w_phi, w_g);
  attn_kernel<<<288, 512>>>();
  outproj_kernel<<<dim3(36, BB), 256, sm3>>>(x, w_out, out);
}